// round 1
// baseline (speedup 1.0000x reference)
#include <cuda_runtime.h>
#include <math.h>

// Problem constants
// B=2, L=64, C=256, S=256, D=512
#define BLn   128           // B*L batches
#define Cn    256
#define Sn    256
#define Dn    512
#define MQ    (BLn * Cn)    // 32768 rows for q / ctx / out
#define MKV   (BLn * Sn)    // 32768 rows for k,v

// Tiling
#define BM 128
#define BN 64
#define BK 16
#define TM 8
#define TN 4
#define NTHREADS 256

// Scratch (static device globals; no dynamic allocation allowed)
__device__ float g_q[(size_t)MQ * Dn];       // 64 MB
__device__ float g_k[(size_t)MKV * Dn];      // 64 MB
__device__ float g_v[(size_t)MKV * Dn];      // 64 MB
__device__ float g_scores[(size_t)BLn * Cn * Sn]; // 32 MB
__device__ float g_ctx[(size_t)MQ * Dn];     // 64 MB

// ---------------------------------------------------------------------------
// Generic tiled GEMM:  C = alpha * A(MxK) * op(B) (+ bias)
//   B_KMAJOR=true : B stored [N,K] row-major (i.e. C = A * B^T)   -- "NT"
//   B_KMAJOR=false: B stored [K,N] row-major (i.e. C = A * B)     -- "NN"
// Batched via blockIdx.z with element strides sA/sB/sC.
// Requires M%BM==0, N%BN==0, K%BK==0 (true for all uses here).
// ---------------------------------------------------------------------------
template <bool B_KMAJOR, bool HAS_BIAS>
__global__ __launch_bounds__(NTHREADS, 2)
void gemm_kernel(const float* __restrict__ A,
                 const float* __restrict__ B,
                 const float* __restrict__ bias,
                 float* __restrict__ C,
                 int M, int N, int K, float alpha,
                 long long sA, long long sB, long long sC)
{
    const float* Ab = A + (long long)blockIdx.z * sA;
    const float* Bb = B + (long long)blockIdx.z * sB;
    float*       Cb = C + (long long)blockIdx.z * sC;

    __shared__ float As[BK][BM + 4];
    __shared__ float Bs[BK][BN + 4];

    const int tid = threadIdx.x;
    const int tx  = tid & 15;   // n-dim thread coord (16)
    const int ty  = tid >> 4;   // m-dim thread coord (16)
    const int m0  = blockIdx.y * BM;
    const int n0  = blockIdx.x * BN;

    float acc[TM][TN];
#pragma unroll
    for (int i = 0; i < TM; i++)
#pragma unroll
        for (int j = 0; j < TN; j++) acc[i][j] = 0.0f;

    const int ktiles = K / BK;
    for (int kt = 0; kt < ktiles; kt++) {
        const int kbase = kt * BK;

        // ---- load A tile: BM x BK = 512 float4, 2 per thread ----
#pragma unroll
        for (int r = 0; r < 2; r++) {
            int f   = tid + r * NTHREADS;      // 0..511
            int row = f >> 2;                  // 0..127
            int kq  = f & 3;                   // which float4 in the row
            float4 va = *reinterpret_cast<const float4*>(
                &Ab[(long long)(m0 + row) * K + kbase + kq * 4]);
            As[kq * 4 + 0][row] = va.x;
            As[kq * 4 + 1][row] = va.y;
            As[kq * 4 + 2][row] = va.z;
            As[kq * 4 + 3][row] = va.w;
        }

        // ---- load B tile ----
        if (B_KMAJOR) {
            // B[N,K]: tile BN x BK = 256 float4, 1 per thread
            int row = tid >> 2;                // 0..63 (n)
            int kq  = tid & 3;
            float4 vb = *reinterpret_cast<const float4*>(
                &Bb[(long long)(n0 + row) * K + kbase + kq * 4]);
            Bs[kq * 4 + 0][row] = vb.x;
            Bs[kq * 4 + 1][row] = vb.y;
            Bs[kq * 4 + 2][row] = vb.z;
            Bs[kq * 4 + 3][row] = vb.w;
        } else {
            // B[K,N]: tile BK x BN = 256 float4, 1 per thread
            int kk = tid >> 4;                 // 0..15 (k)
            int nq = tid & 15;                 // 0..15 (float4 within row)
            float4 vb = *reinterpret_cast<const float4*>(
                &Bb[(long long)(kbase + kk) * N + n0 + nq * 4]);
            // row stride of Bs is 68 floats (multiple of 4) -> aligned
            *reinterpret_cast<float4*>(&Bs[kk][nq * 4]) = vb;
        }

        __syncthreads();

        // ---- compute ----
#pragma unroll
        for (int k = 0; k < BK; k++) {
            float a[TM], b[TN];
#pragma unroll
            for (int i = 0; i < TM; i++) a[i] = As[k][ty * TM + i];
#pragma unroll
            for (int j = 0; j < TN; j++) b[j] = Bs[k][tx * TN + j];
#pragma unroll
            for (int i = 0; i < TM; i++)
#pragma unroll
                for (int j = 0; j < TN; j++)
                    acc[i][j] = fmaf(a[i], b[j], acc[i][j]);
        }

        __syncthreads();
    }

    // ---- epilogue ----
#pragma unroll
    for (int i = 0; i < TM; i++) {
        int m = m0 + ty * TM + i;
#pragma unroll
        for (int j = 0; j < TN; j++) {
            int n = n0 + tx * TN + j;
            float v = alpha * acc[i][j];
            if (HAS_BIAS) v += bias[n];
            Cb[(long long)m * N + n] = v;
        }
    }
}

// ---------------------------------------------------------------------------
// Row softmax over rows of length Sn=256. One block (256 threads) per row.
// ---------------------------------------------------------------------------
__global__ __launch_bounds__(256)
void softmax_kernel(float* __restrict__ scores)
{
    __shared__ float red[256];
    const long long row = blockIdx.x;
    const int t = threadIdx.x;

    float v = scores[row * Sn + t];

    // max reduce
    red[t] = v;
    __syncthreads();
#pragma unroll
    for (int s = 128; s > 0; s >>= 1) {
        if (t < s) red[t] = fmaxf(red[t], red[t + s]);
        __syncthreads();
    }
    const float mx = red[0];
    __syncthreads();

    const float e = expf(v - mx);

    // sum reduce
    red[t] = e;
    __syncthreads();
#pragma unroll
    for (int s = 128; s > 0; s >>= 1) {
        if (t < s) red[t] += red[t + s];
        __syncthreads();
    }
    const float inv = 1.0f / red[0];

    scores[row * Sn + t] = e * inv;
}

// ---------------------------------------------------------------------------
extern "C" void kernel_launch(void* const* d_in, const int* in_sizes, int n_in,
                              void* d_out, int out_size)
{
    const float* queries = (const float*)d_in[0]; // [B,L,C,D]
    const float* keys    = (const float*)d_in[1]; // [B,L,S,D]
    const float* values  = (const float*)d_in[2]; // [B,L,S,D]
    const float* Wq      = (const float*)d_in[3]; // [D,D]
    const float* bq      = (const float*)d_in[4]; // [D]
    const float* Wkv     = (const float*)d_in[5]; // [D,D]
    const float* bkv     = (const float*)d_in[6]; // [D]
    const float* Wo      = (const float*)d_in[7]; // [D,D]
    const float* bo      = (const float*)d_in[8]; // [D]
    float* out = (float*)d_out;                   // [B,L,C,D] fp32

    float *pq, *pk, *pv, *ps, *pc;
    cudaGetSymbolAddress((void**)&pq, g_q);
    cudaGetSymbolAddress((void**)&pk, g_k);
    cudaGetSymbolAddress((void**)&pv, g_v);
    cudaGetSymbolAddress((void**)&ps, g_scores);
    cudaGetSymbolAddress((void**)&pc, g_ctx);

    const float scale = 0.04419417382415922f; // 1/sqrt(512)
    dim3 blk(NTHREADS);

    // 1) Projections: X @ W^T + b   (NT, with bias)
    {
        dim3 grid(Dn / BN, MQ / BM, 1);
        gemm_kernel<true, true><<<grid, blk>>>(queries, Wq, bq, pq,
                                               MQ, Dn, Dn, 1.0f, 0, 0, 0);
        gemm_kernel<true, true><<<grid, blk>>>(keys, Wkv, bkv, pk,
                                               MKV, Dn, Dn, 1.0f, 0, 0, 0);
        gemm_kernel<true, true><<<grid, blk>>>(values, Wkv, bkv, pv,
                                               MKV, Dn, Dn, 1.0f, 0, 0, 0);
    }

    // 2) scores[bl] = scale * q[bl] @ k[bl]^T   (batched NT, no bias)
    {
        dim3 grid(Sn / BN, Cn / BM, BLn);
        gemm_kernel<true, false><<<grid, blk>>>(pq, pk, nullptr, ps,
                                                Cn, Sn, Dn, scale,
                                                (long long)Cn * Dn,
                                                (long long)Sn * Dn,
                                                (long long)Cn * Sn);
    }

    // 3) softmax over last dim
    softmax_kernel<<<BLn * Cn, 256>>>(ps);

    // 4) ctx[bl] = attn[bl] @ v[bl]   (batched NN, no bias)
    {
        dim3 grid(Dn / BN, Cn / BM, BLn);
        gemm_kernel<false, false><<<grid, blk>>>(ps, pv, nullptr, pc,
                                                 Cn, Dn, Sn, 1.0f,
                                                 (long long)Cn * Sn,
                                                 (long long)Sn * Dn,
                                                 (long long)Cn * Dn);
    }

    // 5) out = ctx @ Wo^T + bo   (NT, with bias)
    {
        dim3 grid(Dn / BN, MQ / BM, 1);
        gemm_kernel<true, true><<<grid, blk>>>(pc, Wo, bo, out,
                                               MQ, Dn, Dn, 1.0f, 0, 0, 0);
    }
}

// round 4
// speedup vs baseline: 2.3676x; 2.3676x over previous
#include <cuda_runtime.h>
#include <cuda_bf16.h>
#include <cstdint>

// Problem constants: B=2, L=64, C=256, S=256, D=512
#define BLn 128
#define Cn  256
#define Sn  256
#define Dn  512
#define MQ  (BLn * Cn)   // 32768
#define MKV (BLn * Sn)   // 32768

using bf16 = __nv_bfloat16;

#define NELEM_QD ((size_t)MQ * Dn)       // 16.7M
#define NELEM_S  ((size_t)BLn * Cn * Sn) // 8.4M
#define NELEM_W  ((size_t)Dn * Dn)

// Static scratch (no dynamic allocation allowed)
__device__ bf16 g_qin_h[NELEM_QD], g_qin_l[NELEM_QD];
__device__ bf16 g_kin_h[NELEM_QD], g_kin_l[NELEM_QD];
__device__ bf16 g_vin_h[NELEM_QD], g_vin_l[NELEM_QD];
__device__ bf16 g_wq_h [NELEM_W],  g_wq_l [NELEM_W];
__device__ bf16 g_wkv_h[NELEM_W],  g_wkv_l[NELEM_W];
__device__ bf16 g_wo_h [NELEM_W],  g_wo_l [NELEM_W];
__device__ bf16 g_q_h[NELEM_QD], g_q_l[NELEM_QD];
__device__ bf16 g_k_h[NELEM_QD], g_k_l[NELEM_QD];
__device__ bf16 g_v_h[NELEM_QD], g_v_l[NELEM_QD];
__device__ bf16 g_s_h[NELEM_S],  g_s_l[NELEM_S];
__device__ bf16 g_c_h[NELEM_QD], g_c_l[NELEM_QD];

// ---------------- helpers ----------------
__device__ __forceinline__ uint32_t smem_to_u32(const void* p) {
    uint32_t a;
    asm("{ .reg .u64 t; cvta.to.shared.u64 t, %1; cvt.u32.u64 %0, t; }"
        : "=r"(a) : "l"(p));
    return a;
}
__device__ __forceinline__ void cpasync16(uint32_t dst, const void* src) {
    asm volatile("cp.async.cg.shared.global [%0], [%1], 16;" :: "r"(dst), "l"(src));
}

#define LDSM_X4(r, addr) \
    asm volatile("ldmatrix.sync.aligned.m8n8.x4.shared.b16 {%0,%1,%2,%3},[%4];" \
        : "=r"((r)[0]), "=r"((r)[1]), "=r"((r)[2]), "=r"((r)[3]) : "r"(addr))
#define LDSM_X4_T(r, addr) \
    asm volatile("ldmatrix.sync.aligned.m8n8.x4.trans.shared.b16 {%0,%1,%2,%3},[%4];" \
        : "=r"((r)[0]), "=r"((r)[1]), "=r"((r)[2]), "=r"((r)[3]) : "r"(addr))

#define MMA_BF16(c, a, b) \
    asm volatile("mma.sync.aligned.m16n8k16.row.col.f32.bf16.bf16.f32 " \
        "{%0,%1,%2,%3},{%4,%5,%6,%7},{%8,%9},{%0,%1,%2,%3};" \
        : "+f"((c)[0]), "+f"((c)[1]), "+f"((c)[2]), "+f"((c)[3]) \
        : "r"((a)[0]), "r"((a)[1]), "r"((a)[2]), "r"((a)[3]), \
          "r"((b)[0]), "r"((b)[1]))

// ---------------- split fp32 -> (bf16 hi, bf16 lo) ----------------
__global__ void __launch_bounds__(256)
split_f32(const float* __restrict__ in, bf16* __restrict__ h,
          bf16* __restrict__ l, size_t n4)
{
    size_t i = blockIdx.x * (size_t)blockDim.x + threadIdx.x;
    if (i >= n4) return;
    float4 v = reinterpret_cast<const float4*>(in)[i];
    float f[4] = {v.x, v.y, v.z, v.w};
    bf16 hh[4], ll[4];
#pragma unroll
    for (int j = 0; j < 4; j++) {
        hh[j] = __float2bfloat16(f[j]);
        ll[j] = __float2bfloat16(f[j] - __bfloat162float(hh[j]));
    }
    reinterpret_cast<__nv_bfloat162*>(h)[2*i]   = __nv_bfloat162(hh[0], hh[1]);
    reinterpret_cast<__nv_bfloat162*>(h)[2*i+1] = __nv_bfloat162(hh[2], hh[3]);
    reinterpret_cast<__nv_bfloat162*>(l)[2*i]   = __nv_bfloat162(ll[0], ll[1]);
    reinterpret_cast<__nv_bfloat162*>(l)[2*i+1] = __nv_bfloat162(ll[2], ll[3]);
}

// ---------------- GEMM on bf16 tensor cores, 3-term split ----------------
// C[M,N] = alpha * A[M,K] * op(B) (+ bias)
//   BNN=0 : B stored [N,K] (K-major)  -> NT
//   BNN=1 : B stored [K,N] (N-major)  -> NN (ldmatrix.trans)
// EPI: 0 = +bias, write (Ch,Cl) pair; 1 = *alpha, write pair; 2 = +bias, write fp32 Cf
// CTA tile 128x128, BK=32, 4 warps (64x64 each). All dims divide exactly.
#define STAGE_B 40960          // Ah(10240) Al(10240) Bh(10240) Bl(10240)
#define DYN_SMEM (2 * STAGE_B) // 81920

template <int BNN, int EPI>
__global__ void __launch_bounds__(128)
tc_gemm(const bf16* __restrict__ Ah, const bf16* __restrict__ Al,
        const bf16* __restrict__ Bh, const bf16* __restrict__ Bl,
        const float* __restrict__ bias,
        bf16* __restrict__ Ch, bf16* __restrict__ Cl, float* __restrict__ Cf,
        int N, int K, float alpha,
        long long sA, long long sB, long long sC)
{
    extern __shared__ char sm[];
    const uint32_t sb = smem_to_u32(sm);

    const int tid = threadIdx.x, lane = tid & 31, wid = tid >> 5;
    const int wm0 = (wid >> 1) * 64, wn0 = (wid & 1) * 64;
    const long long m0 = (long long)blockIdx.y * 128;
    const int n0 = blockIdx.x * 128;

    const bf16* Ahb = Ah + blockIdx.z * sA;
    const bf16* Alb = Al + blockIdx.z * sA;
    const bf16* Bhb = Bh + blockIdx.z * sB;
    const bf16* Blb = Bl + blockIdx.z * sB;

    float acc[4][8][4];
#pragma unroll
    for (int mf = 0; mf < 4; mf++)
#pragma unroll
        for (int nf = 0; nf < 8; nf++)
#pragma unroll
            for (int r = 0; r < 4; r++) acc[mf][nf][r] = 0.0f;

    const int KT = K / 32;

    auto load_stage = [&](int kt, int stage) {
        const int kb = kt * 32;
        const uint32_t s0 = sb + stage * STAGE_B;
        // A tiles: [128 rows][32 bf16], smem row stride 80B; 512 chunks/tile
#pragma unroll
        for (int i = 0; i < 4; i++) {
            int id = tid + i * 128;
            int row = id >> 2, c = id & 3;
            long long g = (m0 + row) * (long long)K + kb + c * 8;
            uint32_t d = s0 + row * 80 + c * 16;
            cpasync16(d,         Ahb + g);
            cpasync16(d + 10240, Alb + g);
        }
        if (!BNN) {
            // B tiles: [128 n-rows][32 bf16], stride 80B
#pragma unroll
            for (int i = 0; i < 4; i++) {
                int id = tid + i * 128;
                int row = id >> 2, c = id & 3;
                long long g = (long long)(n0 + row) * K + kb + c * 8;
                uint32_t d = s0 + 20480 + row * 80 + c * 16;
                cpasync16(d,         Bhb + g);
                cpasync16(d + 10240, Blb + g);
            }
        } else {
            // B tiles: [32 k-rows][128 bf16], smem row stride 272B
#pragma unroll
            for (int i = 0; i < 4; i++) {
                int id = tid + i * 128;
                int row = id >> 4, c = id & 15;
                long long g = (long long)(kb + row) * N + n0 + c * 8;
                uint32_t d = s0 + 20480 + row * 272 + c * 16;
                cpasync16(d,         Bhb + g);
                cpasync16(d + 10240, Blb + g);
            }
        }
        asm volatile("cp.async.commit_group;" ::: "memory");
    };

    load_stage(0, 0);

    // ldmatrix lane address components
    const int g8  = lane >> 3, sub = lane & 7;
    const int a_row  = wm0 + (g8 & 1) * 8 + sub;  // + mf*16
    const int a_coff = (g8 >> 1) * 16;            // + kc*32 (bytes)
    const int bn_row  = wn0 + (g8 >> 1) * 8 + sub;// + p*16   (NT)
    const int bn_coff = (g8 & 1) * 16;            // + kc*32
    const int bk_row  = (g8 & 1) * 8 + sub;       // + kc*16  (NN)
    const int bk_noff = (wn0 + (g8 >> 1) * 8) * 2;// bytes; + p*32

    for (int kt = 0; kt < KT; kt++) {
        const int buf = kt & 1;
        if (kt + 1 < KT) {
            load_stage(kt + 1, buf ^ 1);
            asm volatile("cp.async.wait_group 1;" ::: "memory");
        } else {
            asm volatile("cp.async.wait_group 0;" ::: "memory");
        }
        __syncthreads();

        const uint32_t sA0 = sb + buf * STAGE_B;
        const uint32_t sB0 = sA0 + 20480;

#pragma unroll
        for (int kc = 0; kc < 2; kc++) {
            uint32_t ah[4][4], al[4][4];
#pragma unroll
            for (int mf = 0; mf < 4; mf++) {
                uint32_t ad = sA0 + (uint32_t)(a_row + mf * 16) * 80
                                  + kc * 32 + a_coff;
                LDSM_X4(ah[mf], ad);
                LDSM_X4(al[mf], ad + 10240);
            }
            uint32_t bh[8][2], bl[8][2];
#pragma unroll
            for (int p = 0; p < 4; p++) {
                uint32_t r[4];
                if (!BNN) {
                    uint32_t bd = sB0 + (uint32_t)(bn_row + p * 16) * 80
                                      + kc * 32 + bn_coff;
                    LDSM_X4(r, bd);
                    bh[2*p][0] = r[0]; bh[2*p][1] = r[1];
                    bh[2*p+1][0] = r[2]; bh[2*p+1][1] = r[3];
                    LDSM_X4(r, bd + 10240);
                    bl[2*p][0] = r[0]; bl[2*p][1] = r[1];
                    bl[2*p+1][0] = r[2]; bl[2*p+1][1] = r[3];
                } else {
                    uint32_t bd = sB0 + (uint32_t)(bk_row + kc * 16) * 272
                                      + bk_noff + p * 32;
                    LDSM_X4_T(r, bd);
                    bh[2*p][0] = r[0]; bh[2*p][1] = r[1];
                    bh[2*p+1][0] = r[2]; bh[2*p+1][1] = r[3];
                    LDSM_X4_T(r, bd + 10240);
                    bl[2*p][0] = r[0]; bl[2*p][1] = r[1];
                    bl[2*p+1][0] = r[2]; bl[2*p+1][1] = r[3];
                }
            }
#pragma unroll
            for (int mf = 0; mf < 4; mf++)
#pragma unroll
                for (int nf = 0; nf < 8; nf++) {
                    MMA_BF16(acc[mf][nf], ah[mf], bh[nf]);
                    MMA_BF16(acc[mf][nf], ah[mf], bl[nf]);
                    MMA_BF16(acc[mf][nf], al[mf], bh[nf]);
                }
        }
        __syncthreads();
    }

    // ---- epilogue ----
    const int lr = lane >> 2, lc = lane & 3;
#pragma unroll
    for (int mf = 0; mf < 4; mf++) {
#pragma unroll
        for (int nf = 0; nf < 8; nf++) {
            const long long row = m0 + wm0 + mf * 16 + lr;
            const int col = n0 + wn0 + nf * 8 + lc * 2;
            float v0 = acc[mf][nf][0], v1 = acc[mf][nf][1];
            float v2 = acc[mf][nf][2], v3 = acc[mf][nf][3];
            if (EPI == 1) { v0 *= alpha; v1 *= alpha; v2 *= alpha; v3 *= alpha; }
            else {
                float b0 = bias[col], b1 = bias[col + 1];
                v0 += b0; v1 += b1; v2 += b0; v3 += b1;
            }
            if (EPI == 2) {
                float* Cfb = Cf + blockIdx.z * sC;
                *reinterpret_cast<float2*>(&Cfb[row * N + col])
                    = make_float2(v0, v1);
                *reinterpret_cast<float2*>(&Cfb[(row + 8) * N + col])
                    = make_float2(v2, v3);
            } else {
                bf16* Chb = Ch + blockIdx.z * sC;
                bf16* Clb = Cl + blockIdx.z * sC;
                bf16 h0 = __float2bfloat16(v0);
                bf16 h1 = __float2bfloat16(v1);
                bf16 h2 = __float2bfloat16(v2);
                bf16 h3 = __float2bfloat16(v3);
                bf16 l0 = __float2bfloat16(v0 - __bfloat162float(h0));
                bf16 l1 = __float2bfloat16(v1 - __bfloat162float(h1));
                bf16 l2 = __float2bfloat16(v2 - __bfloat162float(h2));
                bf16 l3 = __float2bfloat16(v3 - __bfloat162float(h3));
                *reinterpret_cast<__nv_bfloat162*>(&Chb[row * N + col])
                    = __nv_bfloat162(h0, h1);
                *reinterpret_cast<__nv_bfloat162*>(&Chb[(row + 8) * N + col])
                    = __nv_bfloat162(h2, h3);
                *reinterpret_cast<__nv_bfloat162*>(&Clb[row * N + col])
                    = __nv_bfloat162(l0, l1);
                *reinterpret_cast<__nv_bfloat162*>(&Clb[(row + 8) * N + col])
                    = __nv_bfloat162(l2, l3);
            }
        }
    }
}

// ---------------- softmax on (hi,lo) scores -> (hi,lo) probs ----------------
__global__ void __launch_bounds__(256)
softmax_pair(bf16* __restrict__ sh, bf16* __restrict__ sl)
{
    __shared__ float red[256];
    const long long row = blockIdx.x;
    const int t = threadIdx.x;
    const long long idx = row * Sn + t;

    float v = __bfloat162float(sh[idx]) + __bfloat162float(sl[idx]);
    red[t] = v;
    __syncthreads();
#pragma unroll
    for (int s = 128; s > 0; s >>= 1) {
        if (t < s) red[t] = fmaxf(red[t], red[t + s]);
        __syncthreads();
    }
    const float mx = red[0];
    __syncthreads();
    const float e = expf(v - mx);
    red[t] = e;
    __syncthreads();
#pragma unroll
    for (int s = 128; s > 0; s >>= 1) {
        if (t < s) red[t] += red[t + s];
        __syncthreads();
    }
    const float p = e * (1.0f / red[0]);
    bf16 h = __float2bfloat16(p);
    bf16 l = __float2bfloat16(p - __bfloat162float(h));
    sh[idx] = h;
    sl[idx] = l;
}

// ---------------- launch ----------------
extern "C" void kernel_launch(void* const* d_in, const int* in_sizes, int n_in,
                              void* d_out, int out_size)
{
    const float* queries = (const float*)d_in[0];
    const float* keys    = (const float*)d_in[1];
    const float* values  = (const float*)d_in[2];
    const float* Wq      = (const float*)d_in[3];
    const float* bq      = (const float*)d_in[4];
    const float* Wkv     = (const float*)d_in[5];
    const float* bkv     = (const float*)d_in[6];
    const float* Wo      = (const float*)d_in[7];
    const float* bo      = (const float*)d_in[8];
    float* out = (float*)d_out;

    bf16 *qin_h, *qin_l, *kin_h, *kin_l, *vin_h, *vin_l;
    bf16 *wq_h, *wq_l, *wkv_h, *wkv_l, *wo_h, *wo_l;
    bf16 *q_h, *q_l, *k_h, *k_l, *v_h, *v_l, *s_h, *s_l, *c_h, *c_l;
    cudaGetSymbolAddress((void**)&qin_h, g_qin_h);
    cudaGetSymbolAddress((void**)&qin_l, g_qin_l);
    cudaGetSymbolAddress((void**)&kin_h, g_kin_h);
    cudaGetSymbolAddress((void**)&kin_l, g_kin_l);
    cudaGetSymbolAddress((void**)&vin_h, g_vin_h);
    cudaGetSymbolAddress((void**)&vin_l, g_vin_l);
    cudaGetSymbolAddress((void**)&wq_h,  g_wq_h);
    cudaGetSymbolAddress((void**)&wq_l,  g_wq_l);
    cudaGetSymbolAddress((void**)&wkv_h, g_wkv_h);
    cudaGetSymbolAddress((void**)&wkv_l, g_wkv_l);
    cudaGetSymbolAddress((void**)&wo_h,  g_wo_h);
    cudaGetSymbolAddress((void**)&wo_l,  g_wo_l);
    cudaGetSymbolAddress((void**)&q_h,   g_q_h);
    cudaGetSymbolAddress((void**)&q_l,   g_q_l);
    cudaGetSymbolAddress((void**)&k_h,   g_k_h);
    cudaGetSymbolAddress((void**)&k_l,   g_k_l);
    cudaGetSymbolAddress((void**)&v_h,   g_v_h);
    cudaGetSymbolAddress((void**)&v_l,   g_v_l);
    cudaGetSymbolAddress((void**)&s_h,   g_s_h);
    cudaGetSymbolAddress((void**)&s_l,   g_s_l);
    cudaGetSymbolAddress((void**)&c_h,   g_c_h);
    cudaGetSymbolAddress((void**)&c_l,   g_c_l);

    cudaFuncSetAttribute(tc_gemm<0,0>, cudaFuncAttributeMaxDynamicSharedMemorySize, DYN_SMEM);
    cudaFuncSetAttribute(tc_gemm<0,1>, cudaFuncAttributeMaxDynamicSharedMemorySize, DYN_SMEM);
    cudaFuncSetAttribute(tc_gemm<0,2>, cudaFuncAttributeMaxDynamicSharedMemorySize, DYN_SMEM);
    cudaFuncSetAttribute(tc_gemm<1,1>, cudaFuncAttributeMaxDynamicSharedMemorySize, DYN_SMEM);

    const float scale = 0.04419417382415922f; // 1/sqrt(512)
    dim3 blk(128);

    // 0) split inputs into bf16 (hi, lo)
    {
        size_t nqd4 = NELEM_QD / 4, nw4 = NELEM_W / 4;
        split_f32<<<(unsigned)(nqd4 / 256), 256>>>(queries, qin_h, qin_l, nqd4);
        split_f32<<<(unsigned)(nqd4 / 256), 256>>>(keys,    kin_h, kin_l, nqd4);
        split_f32<<<(unsigned)(nqd4 / 256), 256>>>(values,  vin_h, vin_l, nqd4);
        split_f32<<<(unsigned)(nw4 / 256), 256>>>(Wq,  wq_h,  wq_l,  nw4);
        split_f32<<<(unsigned)(nw4 / 256), 256>>>(Wkv, wkv_h, wkv_l, nw4);
        split_f32<<<(unsigned)(nw4 / 256), 256>>>(Wo,  wo_h,  wo_l,  nw4);
    }

    // 1) projections (NT, +bias, pair output)
    {
        dim3 grid(Dn / 128, MQ / 128, 1);
        tc_gemm<0,0><<<grid, blk, DYN_SMEM>>>(qin_h, qin_l, wq_h, wq_l, bq,
                                              q_h, q_l, nullptr, Dn, Dn, 1.0f, 0, 0, 0);
        tc_gemm<0,0><<<grid, blk, DYN_SMEM>>>(kin_h, kin_l, wkv_h, wkv_l, bkv,
                                              k_h, k_l, nullptr, Dn, Dn, 1.0f, 0, 0, 0);
        tc_gemm<0,0><<<grid, blk, DYN_SMEM>>>(vin_h, vin_l, wkv_h, wkv_l, bkv,
                                              v_h, v_l, nullptr, Dn, Dn, 1.0f, 0, 0, 0);
    }

    // 2) scores = scale * q @ k^T  (batched NT, pair output)
    {
        dim3 grid(Sn / 128, Cn / 128, BLn);
        tc_gemm<0,1><<<grid, blk, DYN_SMEM>>>(q_h, q_l, k_h, k_l, nullptr,
                                              s_h, s_l, nullptr, Sn, Dn, scale,
                                              (long long)Cn * Dn,
                                              (long long)Sn * Dn,
                                              (long long)Cn * Sn);
    }

    // 3) softmax
    softmax_pair<<<BLn * Cn, 256>>>(s_h, s_l);

    // 4) ctx = attn @ v  (batched NN, pair output)
    {
        dim3 grid(Dn / 128, Cn / 128, BLn);
        tc_gemm<1,1><<<grid, blk, DYN_SMEM>>>(s_h, s_l, v_h, v_l, nullptr,
                                              c_h, c_l, nullptr, Dn, Sn, 1.0f,
                                              (long long)Cn * Sn,
                                              (long long)Sn * Dn,
                                              (long long)Cn * Dn);
    }

    // 5) out = ctx @ Wo^T + bo  (NT, fp32 output)
    {
        dim3 grid(Dn / 128, MQ / 128, 1);
        tc_gemm<0,2><<<grid, blk, DYN_SMEM>>>(c_h, c_l, wo_h, wo_l, bo,
                                              nullptr, nullptr, out, Dn, Dn, 1.0f, 0, 0, 0);
    }
}